// round 9
// baseline (speedup 1.0000x reference)
#include <cuda_runtime.h>
#include <cuda_fp16.h>
#include <cstdint>

#define BB   32
#define CHN  16
#define NN   261
#define MM   256
#define MAT  (MM*MM)
#define NMAT (BB*CHN)

// ---------------- scratch (device globals; no allocs allowed) ----------------
__device__ __align__(256) __half g_Ah  [NMAT * MAT];   // feat fp16 (row-major)
__device__ __align__(256) __half g_B2h [NMAT * MAT];   // B2 row-major fp16
__device__ float g_part[NMAT * 4 * 4];   // [bc][tile 2x2][k: tr2,tr3,tr4,tr5]
__device__ unsigned g_head;              // work-queue head
__device__ unsigned g_cnt[NMAT];         // stage-1 tiles completed per matrix

// ---------------------------- helpers ---------------------------------------
__device__ __forceinline__ uint32_t smem_u32(const void* p) {
    uint32_t a;
    asm("{ .reg .u64 t; cvta.to.shared.u64 t, %1; cvt.u32.u64 %0, t; }" : "=r"(a) : "l"(p));
    return a;
}
#define CP16(dst, src) asm volatile("cp.async.cg.shared.global [%0], [%1], 16;" :: "r"((uint32_t)(dst)), "l"(src))
#define CP_COMMIT()    asm volatile("cp.async.commit_group;" ::: "memory")
#define CP_WAIT(n)     asm volatile("cp.async.wait_group %0;" :: "n"(n) : "memory")

#define MMA_F16(d, a, b) \
    asm volatile("mma.sync.aligned.m16n8k16.row.col.f32.f16.f16.f32 " \
        "{%0,%1,%2,%3},{%4,%5,%6,%7},{%8,%9},{%0,%1,%2,%3};" \
        : "+f"((d)[0]), "+f"((d)[1]), "+f"((d)[2]), "+f"((d)[3]) \
        : "r"((a)[0]), "r"((a)[1]), "r"((a)[2]), "r"((a)[3]), "r"((b)[0]), "r"((b)[1]))

#define LDSM4(r, addr) \
    asm volatile("ldmatrix.sync.aligned.m8n8.x4.shared.b16 {%0,%1,%2,%3}, [%4];" \
        : "=r"((r)[0]), "=r"((r)[1]), "=r"((r)[2]), "=r"((r)[3]) : "r"(addr))

#define LDSM4T(r, addr) \
    asm volatile("ldmatrix.sync.aligned.m8n8.x4.trans.shared.b16 {%0,%1,%2,%3}, [%4];" \
        : "=r"((r)[0]), "=r"((r)[1]), "=r"((r)[2]), "=r"((r)[3]) : "r"(addr))

// ---------------------------------------------------------------------------
// Conv: x[b,261,261] * w[16,1,6,6] + bias -> g_Ah (fp16 row-major)
// Block (0,0,0) also resets the fused-GEMM work queue (graph-replay safe).
// ---------------------------------------------------------------------------
__global__ void __launch_bounds__(256) conv_kernel(const float* __restrict__ x,
                                                   const float* __restrict__ w,
                                                   const float* __restrict__ bias) {
    __shared__ float xs[37][38];
    __shared__ float ws[CHN * 36];
    __shared__ float bs[CHN];
    const int b  = blockIdx.z;
    const int bx = blockIdx.x * 32, by = blockIdx.y * 32;
    const int tx = threadIdx.x, ty = threadIdx.y;
    const int tid = ty * 32 + tx;

    if (blockIdx.x == 0 && blockIdx.y == 0 && blockIdx.z == 0) {
        for (int i = tid; i < NMAT; i += 256) g_cnt[i] = 0;
        if (tid == 0) g_head = 0;
    }

    for (int i = tid; i < 37 * 37; i += 256) {
        int r = i / 37, c = i % 37;
        xs[r][c] = x[b * NN * NN + (by + r) * NN + (bx + c)];
    }
    for (int i = tid; i < CHN * 36; i += 256) ws[i] = w[i];
    if (tid < CHN) bs[tid] = bias[tid];
    __syncthreads();

    float acc[4][CHN];
#pragma unroll
    for (int r = 0; r < 4; r++)
#pragma unroll
        for (int c = 0; c < CHN; c++) acc[r][c] = bs[c];

#pragma unroll
    for (int p = 0; p < 6; p++) {
#pragma unroll
        for (int q = 0; q < 6; q++) {
            float xv[4];
#pragma unroll
            for (int r = 0; r < 4; r++) xv[r] = xs[ty + 8 * r + p][tx + q];
#pragma unroll
            for (int c = 0; c < CHN; c++) {
                float wv = ws[c * 36 + p * 6 + q];
#pragma unroll
                for (int r = 0; r < 4; r++) acc[r][c] += xv[r] * wv;
            }
        }
    }

#pragma unroll
    for (int c = 0; c < CHN; c++) {
        size_t base = (size_t)(b * CHN + c) * MAT;
#pragma unroll
        for (int r = 0; r < 4; r++) {
            int row = by + ty + 8 * r, col = bx + tx;
            g_Ah[base + row * MM + col] = __float2half_rn(acc[r][c]);
        }
    }
}

// ---------------------------------------------------------------------------
// Fused persistent GEMM: work-queue of stage-1 (B2=A@A) and stage-2 (A@B2)
// 128x128 tiles. Stage-2 tiles wait on per-matrix counters (release/acquire).
// ---------------------------------------------------------------------------
#define PADK    40
#define PADN    136
#define CS_PAD  129
#define OFFB    10240u
#define SB      18944u                 // stage bytes: 128*80 + 32*272
#define GEMM_SMEM 75776                // 4 stages; epilogue Cs 66048 < this
#define GDIST   4                      // stage2 of group g queued with stage1 of g+GDIST
#define NPAIR   (64 + GDIST)           // p range
#define NITEMS  (NPAIR * 64)

__device__ __forceinline__ void load_stage(uint32_t st,
        const __half* __restrict__ Ah, const __half* __restrict__ Bsrc,
        int col0, int kb, int tid) {
#pragma unroll
    for (int it = 0; it < 2; ++it) {
        int u = it * 256 + tid;
        int rowA = u >> 2, segA = u & 3;
        uint32_t da = (uint32_t)(rowA * (PADK * 2) + segA * 16);
        CP16(st + da, Ah + rowA * MM + kb * 32 + segA * 8);
        int rowB = u >> 4, segB = u & 15;
        uint32_t db = (uint32_t)(rowB * (PADN * 2) + segB * 16);
        CP16(st + OFFB + db, Bsrc + (size_t)(kb * 32 + rowB) * MM + col0 + segB * 8);
    }
}

__device__ __forceinline__ void run_tile(char* sm, uint32_t sbase, bool is2,
                                         int bc, int tileIdx) {
    const int tid  = threadIdx.x;
    const int lane = tid & 31;
    const int w    = tid >> 5;
    const int wm   = w >> 2;
    const int wn   = w & 3;
    const int bx   = tileIdx & 1, by = tileIdx >> 1;
    const int row0 = by * 128, col0 = bx * 128;
    const bool diag = (bx == by);
    const size_t mbase = (size_t)bc * MAT;

    const __half* Ah   = g_Ah + mbase + (size_t)row0 * MM;
    const __half* Bsrc = (is2 ? g_B2h : g_Ah) + mbase;

    const uint32_t aRowOff = (uint32_t)(((lane & 15) * PADK + ((lane >> 4) << 3)) * 2)
                           + (uint32_t)(wm * 64 * PADK * 2);
    const int krow_lane = (lane & 7) + ((lane >> 3) & 1) * 8;
    const int ncol_lane = (lane >> 4) * 8;
    const uint32_t bRowOff = (uint32_t)(krow_lane * (PADN * 2)
                           + (wn * 32 + ncol_lane) * 2);

    float acc[4][4][4];
#pragma unroll
    for (int mi = 0; mi < 4; mi++)
#pragma unroll
        for (int ni = 0; ni < 4; ni++)
#pragma unroll
            for (int e = 0; e < 4; e++) acc[mi][ni][e] = 0.f;

    load_stage(sbase + 0 * SB, Ah, Bsrc, col0, 0, tid); CP_COMMIT();
    load_stage(sbase + 1 * SB, Ah, Bsrc, col0, 1, tid); CP_COMMIT();
    load_stage(sbase + 2 * SB, Ah, Bsrc, col0, 2, tid); CP_COMMIT();

    for (int kb = 0; kb < 8; ++kb) {
        if (kb < 6) { CP_WAIT(2); }
        else if (kb == 6) { CP_WAIT(1); }
        else { CP_WAIT(0); }
        __syncthreads();
        if (kb + 3 < 8) {
            load_stage(sbase + (uint32_t)((kb + 3) & 3) * SB, Ah, Bsrc, col0, kb + 3, tid);
            CP_COMMIT();
        }

        const uint32_t st = sbase + (uint32_t)(kb & 3) * SB;
        const uint32_t aH = st + aRowOff;
        const uint32_t bB = st + OFFB + bRowOff;

#pragma unroll
        for (int ks = 0; ks < 2; ++ks) {
            uint32_t ah[4][4], bq[2][4];
#pragma unroll
            for (int mi = 0; mi < 4; mi++)
                LDSM4(ah[mi], aH + (uint32_t)(mi * 16 * PADK * 2 + ks * 32));
#pragma unroll
            for (int q = 0; q < 2; q++)
                LDSM4T(bq[q], bB + (uint32_t)(ks * 16 * PADN * 2 + q * 32));
#pragma unroll
            for (int mi = 0; mi < 4; mi++)
#pragma unroll
                for (int ni = 0; ni < 4; ni++)
                    MMA_F16(acc[mi][ni], ah[mi], &bq[ni >> 1][(ni & 1) * 2]);
        }
    }
    __syncthreads();

    // ---------------- epilogue ----------------
    float* Cs  = (float*)sm;                      // [128][129]
    float* red = (float*)(sm + 66048);
#pragma unroll
    for (int mi = 0; mi < 4; mi++)
#pragma unroll
        for (int ni = 0; ni < 4; ni++) {
            int r = wm * 64 + mi * 16 + (lane >> 2);
            int c = wn * 32 + ni * 8 + (lane & 3) * 2;
            Cs[r * CS_PAD + c]           = acc[mi][ni][0];
            Cs[r * CS_PAD + c + 1]       = acc[mi][ni][1];
            Cs[(r + 8) * CS_PAD + c]     = acc[mi][ni][2];
            Cs[(r + 8) * CS_PAD + c + 1] = acc[mi][ni][3];
        }
    __syncthreads();

    float p0 = 0.f, p2 = 0.f, p3 = 0.f;
    if (diag && tid < 128) p0 = Cs[tid * CS_PAD + tid];

    if (!is2) {
        for (int u = tid; u < 8192; u += 256) {
            int i = u >> 6, j2 = (u & 63) * 2;
            float v0 = Cs[i * CS_PAD + j2], v1 = Cs[i * CS_PAD + j2 + 1];
            size_t o = mbase + (size_t)(row0 + i) * MM + col0 + j2;
            *(__half2*)&g_B2h[o] = __halves2half2(__float2half_rn(v0), __float2half_rn(v1));
        }
    } else {
        for (int u = tid; u < 8192; u += 256) {
            int jj = u >> 6, ii2 = (u & 63) * 2;
            size_t o = mbase + (size_t)(col0 + jj) * MM + row0 + ii2;
            float2 at = __half22float2(*(const __half2*)&g_Ah[o]);
            float2 bt = __half22float2(*(const __half2*)&g_B2h[o]);
            float c0 = Cs[ii2 * CS_PAD + jj];
            float c1 = Cs[(ii2 + 1) * CS_PAD + jj];
            p2 += c0 * at.x + c1 * at.y;      // tr(A^4)
            p3 += c0 * bt.x + c1 * bt.y;      // tr(A^5)
        }
    }

#pragma unroll
    for (int off = 16; off; off >>= 1) {
        p0 += __shfl_down_sync(0xFFFFFFFFu, p0, off);
        p2 += __shfl_down_sync(0xFFFFFFFFu, p2, off);
        p3 += __shfl_down_sync(0xFFFFFFFFu, p3, off);
    }
    __syncthreads();
    if (lane == 0) {
        red[w * 3 + 0] = p0; red[w * 3 + 1] = p2; red[w * 3 + 2] = p3;
    }
    __syncthreads();
    if (tid == 0) {
        float s0 = 0.f, s2 = 0.f, s3 = 0.f;
        for (int q = 0; q < 8; q++) {
            s0 += red[q * 3]; s2 += red[q * 3 + 1]; s3 += red[q * 3 + 2];
        }
        int slot = (bc * 4 + (by * 2 + bx)) * 4;
        if (!is2) g_part[slot + 0] = s0;
        else { g_part[slot + 1] = s0; g_part[slot + 2] = s2; g_part[slot + 3] = s3; }
    }

    if (!is2) {
        // release: B2 tile visible before counter bump
        __threadfence();
        __syncthreads();
        if (tid == 0) atomicAdd(&g_cnt[bc], 1);
    }
}

__global__ void __launch_bounds__(256, 2) fused_gemm_kernel() {
    extern __shared__ char sm[];
    const uint32_t sbase = smem_u32(sm);
    __shared__ unsigned s_item;
    const int tid = threadIdx.x;

    while (true) {
        if (tid == 0) s_item = atomicAdd(&g_head, 1u);
        __syncthreads();
        unsigned idx = s_item;
        if (idx >= NITEMS) break;
        int p = (int)(idx >> 6), r = (int)(idx & 63);
        bool is2; int bc, tileIdx;
        if (r < 32) {
            if (p >= 64) continue;           // noop tail
            is2 = false; bc = p * 8 + (r >> 2); tileIdx = r & 3;
        } else {
            if (p < GDIST) continue;         // noop head
            is2 = true; bc = (p - GDIST) * 8 + ((r - 32) >> 2); tileIdx = (r - 32) & 3;
        }

        if (is2) {
            if (tid == 0) {
                unsigned v;
                do {
                    asm volatile("ld.acquire.gpu.u32 %0, [%1];"
                                 : "=r"(v) : "l"(g_cnt + bc) : "memory");
                    if (v < 4u) __nanosleep(64);
                } while (v < 4u);
            }
            __syncthreads();
        }
        run_tile(sm, sbase, is2, bc, tileIdx);
        __syncthreads();
    }
}

// ---------------------------------------------------------------------------
// Combine: out[b] = sum coef[c,i,j] * tr_{i+2}^(j+1) / 65536^(i+j+1)
// ---------------------------------------------------------------------------
__global__ void __launch_bounds__(512) final_kernel(const float* __restrict__ coef,
                                                    float* __restrict__ out) {
    int t = threadIdx.x;
    int b = t >> 4, c = t & 15;
    int bc = b * CHN + c;
    double tr[4];
#pragma unroll
    for (int k = 0; k < 4; k++) {
        float s = 0.f;
#pragma unroll
        for (int tile = 0; tile < 4; tile++) s += g_part[(bc * 4 + tile) * 4 + k];
        tr[k] = (double)s;
    }
    double sum = 0.0;
#pragma unroll
    for (int i = 0; i < 4; i++) {
        double p = tr[i];
        double tp = p;
#pragma unroll
        for (int j = 0; j < 4; j++) {
            double v = ldexp(tp, -16 * (i + j + 1));
            sum += (double)coef[c * 16 + i * 4 + j] * v;
            tp *= p;
        }
    }
#pragma unroll
    for (int off = 8; off; off >>= 1)
        sum += __shfl_down_sync(0xFFFFFFFFu, sum, off, 16);
    if (c == 0) out[b] = (float)sum;
}

extern "C" void kernel_launch(void* const* d_in, const int* in_sizes, int n_in,
                              void* d_out, int out_size) {
    const float* x    = (const float*)d_in[0];
    const float* w    = (const float*)d_in[1];
    const float* bias = (const float*)d_in[2];
    const float* coef = (const float*)d_in[3];
    float* out = (float*)d_out;

    cudaFuncSetAttribute(fused_gemm_kernel, cudaFuncAttributeMaxDynamicSharedMemorySize, GEMM_SMEM);

    conv_kernel<<<dim3(8, 8, BB), dim3(32, 8)>>>(x, w, bias);
    fused_gemm_kernel<<<296, 256, GEMM_SMEM>>>();
    final_kernel<<<1, 512>>>(coef, out);
}

// round 10
// speedup vs baseline: 1.1410x; 1.1410x over previous
#include <cuda_runtime.h>
#include <cuda_fp16.h>
#include <cstdint>

#define BB   32
#define CHN  16
#define NN   261
#define MM   256
#define MAT  (MM*MM)
#define NMAT (BB*CHN)

// ---------------- scratch (device globals; no allocs allowed) ----------------
__device__ __align__(256) __half g_Ah  [NMAT * MAT];   // feat fp16 (row-major)
__device__ __align__(256) __half g_B2h [NMAT * MAT];   // B2 row-major fp16
__device__ float g_part[NMAT * 4 * 4];   // [bc][tile 2x2][k: tr2,tr3,tr4,tr5]

// ---------------------------- helpers ---------------------------------------
__device__ __forceinline__ uint32_t smem_u32(const void* p) {
    uint32_t a;
    asm("{ .reg .u64 t; cvta.to.shared.u64 t, %1; cvt.u32.u64 %0, t; }" : "=r"(a) : "l"(p));
    return a;
}
#define CP16(dst, src) asm volatile("cp.async.cg.shared.global [%0], [%1], 16;" :: "r"((uint32_t)(dst)), "l"(src))
#define CP_COMMIT()    asm volatile("cp.async.commit_group;" ::: "memory")
#define CP_WAIT(n)     asm volatile("cp.async.wait_group %0;" :: "n"(n) : "memory")

#define MMA_F16(d, a, b) \
    asm volatile("mma.sync.aligned.m16n8k16.row.col.f32.f16.f16.f32 " \
        "{%0,%1,%2,%3},{%4,%5,%6,%7},{%8,%9},{%0,%1,%2,%3};" \
        : "+f"((d)[0]), "+f"((d)[1]), "+f"((d)[2]), "+f"((d)[3]) \
        : "r"((a)[0]), "r"((a)[1]), "r"((a)[2]), "r"((a)[3]), "r"((b)[0]), "r"((b)[1]))

#define LDSM4(r, addr) \
    asm volatile("ldmatrix.sync.aligned.m8n8.x4.shared.b16 {%0,%1,%2,%3}, [%4];" \
        : "=r"((r)[0]), "=r"((r)[1]), "=r"((r)[2]), "=r"((r)[3]) : "r"(addr))

#define LDSM4T(r, addr) \
    asm volatile("ldmatrix.sync.aligned.m8n8.x4.trans.shared.b16 {%0,%1,%2,%3}, [%4];" \
        : "=r"((r)[0]), "=r"((r)[1]), "=r"((r)[2]), "=r"((r)[3]) : "r"(addr))

// ---------------------------------------------------------------------------
// Conv: x[b,261,261] * w[16,1,6,6] + bias -> g_Ah (fp16 row-major)
// Channel-split: each block does 8 of the 16 channels (grid.z = B*2) so the
// accumulator block is 4x8 -> ~half the registers -> 2 CTAs/SM.
// ---------------------------------------------------------------------------
__global__ void __launch_bounds__(256, 2) conv_kernel(const float* __restrict__ x,
                                                      const float* __restrict__ w,
                                                      const float* __restrict__ bias) {
    __shared__ float xs[37][38];
    __shared__ float ws[8 * 36];
    __shared__ float bs[8];
    const int b   = blockIdx.z >> 1;
    const int ch0 = (blockIdx.z & 1) * 8;
    const int bx = blockIdx.x * 32, by = blockIdx.y * 32;
    const int tx = threadIdx.x, ty = threadIdx.y;
    const int tid = ty * 32 + tx;

    for (int i = tid; i < 37 * 37; i += 256) {
        int r = i / 37, c = i % 37;
        xs[r][c] = x[b * NN * NN + (by + r) * NN + (bx + c)];
    }
    for (int i = tid; i < 8 * 36; i += 256) ws[i] = w[ch0 * 36 + i];
    if (tid < 8) bs[tid] = bias[ch0 + tid];
    __syncthreads();

    float acc[4][8];
#pragma unroll
    for (int r = 0; r < 4; r++)
#pragma unroll
        for (int c = 0; c < 8; c++) acc[r][c] = bs[c];

#pragma unroll
    for (int p = 0; p < 6; p++) {
#pragma unroll
        for (int q = 0; q < 6; q++) {
            float xv[4];
#pragma unroll
            for (int r = 0; r < 4; r++) xv[r] = xs[ty + 8 * r + p][tx + q];
#pragma unroll
            for (int c = 0; c < 8; c++) {
                float wv = ws[c * 36 + p * 6 + q];
#pragma unroll
                for (int r = 0; r < 4; r++) acc[r][c] += xv[r] * wv;
            }
        }
    }

#pragma unroll
    for (int c = 0; c < 8; c++) {
        size_t base = (size_t)(b * CHN + ch0 + c) * MAT;
#pragma unroll
        for (int r = 0; r < 4; r++) {
            int row = by + ty + 8 * r, col = bx + tx;
            g_Ah[base + row * MM + col] = __float2half_rn(acc[r][c]);
        }
    }
}

// ---------------------------------------------------------------------------
// fp16 mma.sync GEMM, 128x128 tile, BK=32, 4-stage cp.async ring, 1-term.
// IS2=0: C = Ah@Ah   -> write B2 fp16 row-major + tr2 diag partial
// IS2=1: C = Ah@B2h  -> tr3 diag; tr4 = sum C*A^T; tr5 = sum C*B2^T
// ---------------------------------------------------------------------------
#define PADK    40                     // A halves per row (32 + 8 pad); 80B stride
#define PADN    136                    // B halves per row (128 + 8 pad); 272B stride
#define CS_PAD  129
#define OFFB    10240u
#define SB      18944u                 // stage bytes: 128*80 + 32*272
#define GEMM_SMEM 75776                // 4 stages; epilogue needs 66144 < this

__device__ __forceinline__ void load_stage(uint32_t st,
        const __half* __restrict__ Ah, const __half* __restrict__ Bsrc,
        int col0, int kb, int tid) {
#pragma unroll
    for (int it = 0; it < 2; ++it) {
        int u = it * 256 + tid;          // 0..511
        int rowA = u >> 2, segA = u & 3;
        uint32_t da = (uint32_t)(rowA * (PADK * 2) + segA * 16);
        CP16(st + da, Ah + rowA * MM + kb * 32 + segA * 8);
        int rowB = u >> 4, segB = u & 15;
        uint32_t db = (uint32_t)(rowB * (PADN * 2) + segB * 16);
        CP16(st + OFFB + db, Bsrc + (size_t)(kb * 32 + rowB) * MM + col0 + segB * 8);
    }
}

template <bool IS2>
__global__ void __launch_bounds__(256, 2) gemm_kernel() {
    extern __shared__ char sm[];
    const uint32_t sbase = smem_u32(sm);
    const int tid  = threadIdx.x;
    const int lane = tid & 31;
    const int w    = tid >> 5;
    const int wm   = w >> 2;            // 0..1 -> 64-row slab
    const int wn   = w & 3;             // 0..3 -> 32-col slab
    const int bc   = blockIdx.z;
    const int row0 = blockIdx.y * 128;
    const int col0 = blockIdx.x * 128;
    const bool diag = (blockIdx.x == blockIdx.y);
    const size_t mbase = (size_t)bc * MAT;

    const __half* Ah = g_Ah + mbase + (size_t)row0 * MM;
    const __half* Bsrc = (IS2 ? g_B2h : g_Ah) + mbase;   // row-major; rows = k

    const uint32_t aRowOff = (uint32_t)(((lane & 15) * PADK + ((lane >> 4) << 3)) * 2)
                           + (uint32_t)(wm * 64 * PADK * 2);
    const int krow_lane = (lane & 7) + ((lane >> 3) & 1) * 8;   // 0..15
    const int ncol_lane = (lane >> 4) * 8;                       // 0 or 8
    const uint32_t bRowOff = (uint32_t)(krow_lane * (PADN * 2)
                           + (wn * 32 + ncol_lane) * 2);

    float acc[4][4][4];
#pragma unroll
    for (int mi = 0; mi < 4; mi++)
#pragma unroll
        for (int ni = 0; ni < 4; ni++)
#pragma unroll
            for (int e = 0; e < 4; e++) acc[mi][ni][e] = 0.f;

    load_stage(sbase + 0 * SB, Ah, Bsrc, col0, 0, tid); CP_COMMIT();
    load_stage(sbase + 1 * SB, Ah, Bsrc, col0, 1, tid); CP_COMMIT();
    load_stage(sbase + 2 * SB, Ah, Bsrc, col0, 2, tid); CP_COMMIT();

    for (int kb = 0; kb < 8; ++kb) {
        if (kb < 6) { CP_WAIT(2); }
        else if (kb == 6) { CP_WAIT(1); }
        else { CP_WAIT(0); }
        __syncthreads();
        if (kb + 3 < 8) {
            load_stage(sbase + (uint32_t)((kb + 3) & 3) * SB, Ah, Bsrc, col0, kb + 3, tid);
            CP_COMMIT();
        }

        const uint32_t st = sbase + (uint32_t)(kb & 3) * SB;
        const uint32_t aH = st + aRowOff;
        const uint32_t bB = st + OFFB + bRowOff;

#pragma unroll
        for (int ks = 0; ks < 2; ++ks) {
            uint32_t ah[4][4], bq[2][4];
#pragma unroll
            for (int mi = 0; mi < 4; mi++)
                LDSM4(ah[mi], aH + (uint32_t)(mi * 16 * PADK * 2 + ks * 32));
#pragma unroll
            for (int q = 0; q < 2; q++)
                LDSM4T(bq[q], bB + (uint32_t)(ks * 16 * PADN * 2 + q * 32));
#pragma unroll
            for (int mi = 0; mi < 4; mi++)
#pragma unroll
                for (int ni = 0; ni < 4; ni++)
                    MMA_F16(acc[mi][ni], ah[mi], &bq[ni >> 1][(ni & 1) * 2]);
        }
    }
    __syncthreads();

    // ---------------- epilogue: stage C through smem ----------------
    float* Cs  = (float*)sm;                      // [128][129]
    float* red = (float*)(sm + 66048);
#pragma unroll
    for (int mi = 0; mi < 4; mi++)
#pragma unroll
        for (int ni = 0; ni < 4; ni++) {
            int r = wm * 64 + mi * 16 + (lane >> 2);
            int c = wn * 32 + ni * 8 + (lane & 3) * 2;
            Cs[r * CS_PAD + c]           = acc[mi][ni][0];
            Cs[r * CS_PAD + c + 1]       = acc[mi][ni][1];
            Cs[(r + 8) * CS_PAD + c]     = acc[mi][ni][2];
            Cs[(r + 8) * CS_PAD + c + 1] = acc[mi][ni][3];
        }
    __syncthreads();

    float p0 = 0.f;                     // tr2 (!IS2) or tr3 (IS2), from diag
    float p2 = 0.f, p3 = 0.f;           // tr4, tr5 (IS2 only)

    if (diag && tid < 128) p0 = Cs[tid * CS_PAD + tid];

    if (!IS2) {
        for (int u = tid; u < 8192; u += 256) {
            int i = u >> 6, j2 = (u & 63) * 2;
            float v0 = Cs[i * CS_PAD + j2], v1 = Cs[i * CS_PAD + j2 + 1];
            size_t o = mbase + (size_t)(row0 + i) * MM + col0 + j2;
            *(__half2*)&g_B2h[o] = __halves2half2(__float2half_rn(v0), __float2half_rn(v1));
        }
    } else {
        // tr4 = sum C[r][c] * A[c][r] ; tr5 = sum C[r][c] * B2[c][r]
        for (int u = tid; u < 8192; u += 256) {
            int jj = u >> 6, ii2 = (u & 63) * 2;
            size_t o = mbase + (size_t)(col0 + jj) * MM + row0 + ii2;
            float2 at = __half22float2(*(const __half2*)&g_Ah[o]);
            float2 bt = __half22float2(*(const __half2*)&g_B2h[o]);
            float c0 = Cs[ii2 * CS_PAD + jj];
            float c1 = Cs[(ii2 + 1) * CS_PAD + jj];
            p2 += c0 * at.x + c1 * at.y;      // tr(A^4)
            p3 += c0 * bt.x + c1 * bt.y;      // tr(A^5)
        }
    }

    // deterministic block reduce
#pragma unroll
    for (int off = 16; off; off >>= 1) {
        p0 += __shfl_down_sync(0xFFFFFFFFu, p0, off);
        p2 += __shfl_down_sync(0xFFFFFFFFu, p2, off);
        p3 += __shfl_down_sync(0xFFFFFFFFu, p3, off);
    }
    __syncthreads();
    if (lane == 0) {
        red[w * 3 + 0] = p0; red[w * 3 + 1] = p2; red[w * 3 + 2] = p3;
    }
    __syncthreads();
    if (tid == 0) {
        float s0 = 0.f, s2 = 0.f, s3 = 0.f;
        for (int q = 0; q < 8; q++) {
            s0 += red[q * 3]; s2 += red[q * 3 + 1]; s3 += red[q * 3 + 2];
        }
        int slot = (bc * 4 + (int)(blockIdx.y * 2 + blockIdx.x)) * 4;
        if (!IS2) g_part[slot + 0] = s0;
        else { g_part[slot + 1] = s0; g_part[slot + 2] = s2; g_part[slot + 3] = s3; }
    }
}

// ---------------------------------------------------------------------------
// Combine: out[b] = sum coef[c,i,j] * tr_{i+2}^(j+1) / 65536^(i+j+1)
// ---------------------------------------------------------------------------
__global__ void __launch_bounds__(512) final_kernel(const float* __restrict__ coef,
                                                    float* __restrict__ out) {
    int t = threadIdx.x;
    int b = t >> 4, c = t & 15;
    int bc = b * CHN + c;
    double tr[4];
#pragma unroll
    for (int k = 0; k < 4; k++) {
        float s = 0.f;
#pragma unroll
        for (int tile = 0; tile < 4; tile++) s += g_part[(bc * 4 + tile) * 4 + k];
        tr[k] = (double)s;
    }
    double sum = 0.0;
#pragma unroll
    for (int i = 0; i < 4; i++) {
        double p = tr[i];
        double tp = p;
#pragma unroll
        for (int j = 0; j < 4; j++) {
            double v = ldexp(tp, -16 * (i + j + 1));
            sum += (double)coef[c * 16 + i * 4 + j] * v;
            tp *= p;
        }
    }
#pragma unroll
    for (int off = 8; off; off >>= 1)
        sum += __shfl_down_sync(0xFFFFFFFFu, sum, off, 16);
    if (c == 0) out[b] = (float)sum;
}

extern "C" void kernel_launch(void* const* d_in, const int* in_sizes, int n_in,
                              void* d_out, int out_size) {
    const float* x    = (const float*)d_in[0];
    const float* w    = (const float*)d_in[1];
    const float* bias = (const float*)d_in[2];
    const float* coef = (const float*)d_in[3];
    float* out = (float*)d_out;

    cudaFuncSetAttribute(gemm_kernel<false>, cudaFuncAttributeMaxDynamicSharedMemorySize, GEMM_SMEM);
    cudaFuncSetAttribute(gemm_kernel<true>,  cudaFuncAttributeMaxDynamicSharedMemorySize, GEMM_SMEM);

    conv_kernel<<<dim3(8, 8, BB * 2), dim3(32, 8)>>>(x, w, bias);
    gemm_kernel<false><<<dim3(2, 2, NMAT), 256, GEMM_SMEM>>>();
    gemm_kernel<true> <<<dim3(2, 2, NMAT), 256, GEMM_SMEM>>>();
    final_kernel<<<1, 512>>>(coef, out);
}

// round 12
// speedup vs baseline: 1.2157x; 1.0655x over previous
#include <cuda_runtime.h>
#include <cuda_fp16.h>
#include <cstdint>

#define BB   32
#define CHN  16
#define NN   261
#define MM   256
#define MAT  (MM*MM)
#define NMAT (BB*CHN)

// ---------------- scratch (device globals; no allocs allowed) ----------------
__device__ __align__(256) __half g_Ah  [NMAT * MAT];   // feat fp16 (row-major)
__device__ __align__(256) __half g_B2h [NMAT * MAT];   // B2 row-major fp16
__device__ float g_part[NMAT * 4 * 4];   // [bc][tile 2x2][k: tr2,tr3,tr4,tr5]

// ---------------------------- helpers ---------------------------------------
__device__ __forceinline__ uint32_t smem_u32(const void* p) {
    uint32_t a;
    asm("{ .reg .u64 t; cvta.to.shared.u64 t, %1; cvt.u32.u64 %0, t; }" : "=r"(a) : "l"(p));
    return a;
}
#define CP16(dst, src) asm volatile("cp.async.cg.shared.global [%0], [%1], 16;" :: "r"((uint32_t)(dst)), "l"(src))
#define CP_COMMIT()    asm volatile("cp.async.commit_group;" ::: "memory")
#define CP_WAIT(n)     asm volatile("cp.async.wait_group %0;" :: "n"(n) : "memory")

#define MMA_F16(d, a, b) \
    asm volatile("mma.sync.aligned.m16n8k16.row.col.f32.f16.f16.f32 " \
        "{%0,%1,%2,%3},{%4,%5,%6,%7},{%8,%9},{%0,%1,%2,%3};" \
        : "+f"((d)[0]), "+f"((d)[1]), "+f"((d)[2]), "+f"((d)[3]) \
        : "r"((a)[0]), "r"((a)[1]), "r"((a)[2]), "r"((a)[3]), "r"((b)[0]), "r"((b)[1]))

#define LDSM4(r, addr) \
    asm volatile("ldmatrix.sync.aligned.m8n8.x4.shared.b16 {%0,%1,%2,%3}, [%4];" \
        : "=r"((r)[0]), "=r"((r)[1]), "=r"((r)[2]), "=r"((r)[3]) : "r"(addr))

#define LDSM4T(r, addr) \
    asm volatile("ldmatrix.sync.aligned.m8n8.x4.trans.shared.b16 {%0,%1,%2,%3}, [%4];" \
        : "=r"((r)[0]), "=r"((r)[1]), "=r"((r)[2]), "=r"((r)[3]) : "r"(addr))

// ---------------------------------------------------------------------------
// Conv: x[b,261,261] * w[16,1,6,6] + bias -> g_Ah (fp16 row-major)
// Channel-split: 8 channels per block (grid.z = B*2).
// ---------------------------------------------------------------------------
__global__ void __launch_bounds__(256, 2) conv_kernel(const float* __restrict__ x,
                                                      const float* __restrict__ w,
                                                      const float* __restrict__ bias) {
    __shared__ float xs[37][38];
    __shared__ float ws[8 * 36];
    __shared__ float bs[8];
    const int b   = blockIdx.z >> 1;
    const int ch0 = (blockIdx.z & 1) * 8;
    const int bx = blockIdx.x * 32, by = blockIdx.y * 32;
    const int tx = threadIdx.x, ty = threadIdx.y;
    const int tid = ty * 32 + tx;

    for (int i = tid; i < 37 * 37; i += 256) {
        int r = i / 37, c = i % 37;
        xs[r][c] = x[b * NN * NN + (by + r) * NN + (bx + c)];
    }
    for (int i = tid; i < 8 * 36; i += 256) ws[i] = w[ch0 * 36 + i];
    if (tid < 8) bs[tid] = bias[ch0 + tid];
    __syncthreads();

    float acc[4][8];
#pragma unroll
    for (int r = 0; r < 4; r++)
#pragma unroll
        for (int c = 0; c < 8; c++) acc[r][c] = bs[c];

#pragma unroll
    for (int p = 0; p < 6; p++) {
#pragma unroll
        for (int q = 0; q < 6; q++) {
            float xv[4];
#pragma unroll
            for (int r = 0; r < 4; r++) xv[r] = xs[ty + 8 * r + p][tx + q];
#pragma unroll
            for (int c = 0; c < 8; c++) {
                float wv = ws[c * 36 + p * 6 + q];
#pragma unroll
                for (int r = 0; r < 4; r++) acc[r][c] += xv[r] * wv;
            }
        }
    }

#pragma unroll
    for (int c = 0; c < 8; c++) {
        size_t base = (size_t)(b * CHN + ch0 + c) * MAT;
#pragma unroll
        for (int r = 0; r < 4; r++) {
            int row = by + ty + 8 * r, col = bx + tx;
            g_Ah[base + row * MM + col] = __float2half_rn(acc[r][c]);
        }
    }
}

// ---------------------------------------------------------------------------
// fp16 mma.sync GEMM, 128x128 tile, BK=32, 4-stage cp.async ring, no epilogue
// staging.
// IS2=0: C = A@A. Fragments stored straight to g_B2h (half2) + inline tr2.
// IS2=1: D = C^T computed directly by swapping which operand is .trans:
//        A-op = B2 tile (k-major, LDSM4T), B-op = A rows (row-major, LDSM4).
//        Thread holding D[j,i]=C[i,j] reads A[j,i], B2[j,i] at its own
//        fragment position (aligned half2) -> tr4/tr5; inline diag tr3.
// ---------------------------------------------------------------------------
#define PADK    40                     // A halves per row (32 + 8 pad); 80B stride
#define PADN    136                    // B halves per row (128 + 8 pad); 272B stride
#define OFFB    10240u
#define SB      18944u                 // stage bytes: 128*80 + 32*272
#define GEMM_SMEM 75776                // 4 stages

__device__ __forceinline__ void load_stage(uint32_t st,
        const __half* __restrict__ Ah, const __half* __restrict__ Bsrc,
        int col0, int kb, int tid) {
#pragma unroll
    for (int it = 0; it < 2; ++it) {
        int u = it * 256 + tid;          // 0..511
        int rowA = u >> 2, segA = u & 3;
        uint32_t da = (uint32_t)(rowA * (PADK * 2) + segA * 16);
        CP16(st + da, Ah + rowA * MM + kb * 32 + segA * 8);
        int rowB = u >> 4, segB = u & 15;
        uint32_t db = (uint32_t)(rowB * (PADN * 2) + segB * 16);
        CP16(st + OFFB + db, Bsrc + (size_t)(kb * 32 + rowB) * MM + col0 + segB * 8);
    }
}

template <bool IS2>
__global__ void __launch_bounds__(256, 2) gemm_kernel() {
    extern __shared__ char sm[];
    const uint32_t sbase = smem_u32(sm);
    const int tid  = threadIdx.x;
    const int lane = tid & 31;
    const int w    = tid >> 5;
    const int wm   = w >> 2;            // 0..1 -> 64-wide m slab
    const int wn   = w & 3;             // 0..3 -> 32-wide n slab
    const int bc   = blockIdx.z;
    const int row0 = blockIdx.y * 128;
    const int col0 = blockIdx.x * 128;
    const bool diag = (blockIdx.x == blockIdx.y);
    const size_t mbase = (size_t)bc * MAT;

    const __half* Ah = g_Ah + mbase + (size_t)row0 * MM;
    const __half* Bsrc = (IS2 ? g_B2h : g_Ah) + mbase;   // row-major; rows = k

    // --- lane offsets ---
    // g1: A-op = OFF_A non-trans (m16k16), B-op = OFFB trans (n16k16)
    // g2: A-op = OFFB trans (m=j),        B-op = OFF_A non-trans (n=i)
    uint32_t aOff, bOff;
    if (!IS2) {
        aOff = (uint32_t)(((lane & 15) * PADK + ((lane >> 4) << 3)) * 2)
             + (uint32_t)(wm * 64 * PADK * 2);
        bOff = OFFB
             + (uint32_t)(((lane & 7) + ((lane >> 3) & 1) * 8) * (PADN * 2)
             + (wn * 32 + (lane >> 4) * 8) * 2);
    } else {
        aOff = OFFB
             + (uint32_t)(((lane & 7) + ((lane >> 4) << 3)) * (PADN * 2)
             + (wm * 64 + ((lane >> 3) & 1) * 8) * 2);
        bOff = (uint32_t)((wn * 32 + (lane & 7) + ((lane >> 4) << 3)) * (PADK * 2)
             + ((lane >> 3) & 1) * 16);
    }

    float acc[4][4][4];
#pragma unroll
    for (int mi = 0; mi < 4; mi++)
#pragma unroll
        for (int ni = 0; ni < 4; ni++)
#pragma unroll
            for (int e = 0; e < 4; e++) acc[mi][ni][e] = 0.f;

    load_stage(sbase + 0 * SB, Ah, Bsrc, col0, 0, tid); CP_COMMIT();
    load_stage(sbase + 1 * SB, Ah, Bsrc, col0, 1, tid); CP_COMMIT();
    load_stage(sbase + 2 * SB, Ah, Bsrc, col0, 2, tid); CP_COMMIT();

    for (int kb = 0; kb < 8; ++kb) {
        if (kb < 6) { CP_WAIT(2); }
        else if (kb == 6) { CP_WAIT(1); }
        else { CP_WAIT(0); }
        __syncthreads();
        if (kb + 3 < 8) {
            load_stage(sbase + (uint32_t)((kb + 3) & 3) * SB, Ah, Bsrc, col0, kb + 3, tid);
            CP_COMMIT();
        }

        const uint32_t st = sbase + (uint32_t)(kb & 3) * SB;

#pragma unroll
        for (int ks = 0; ks < 2; ++ks) {
            uint32_t af[4][4], bq[2][4];
            if (!IS2) {
#pragma unroll
                for (int mi = 0; mi < 4; mi++)
                    LDSM4(af[mi], st + aOff + (uint32_t)(mi * 16 * PADK * 2 + ks * 32));
#pragma unroll
                for (int q = 0; q < 2; q++)
                    LDSM4T(bq[q], st + bOff + (uint32_t)(ks * 16 * PADN * 2 + q * 16 * 2));
            } else {
#pragma unroll
                for (int mi = 0; mi < 4; mi++)
                    LDSM4T(af[mi], st + aOff + (uint32_t)(ks * 16 * PADN * 2 + mi * 16 * 2));
#pragma unroll
                for (int q = 0; q < 2; q++)
                    LDSM4(bq[q], st + bOff + (uint32_t)(q * 16 * PADK * 2 + ks * 32));
            }
#pragma unroll
            for (int mi = 0; mi < 4; mi++)
#pragma unroll
                for (int ni = 0; ni < 4; ni++)
                    MMA_F16(acc[mi][ni], af[mi], &bq[ni >> 1][(ni & 1) * 2]);
        }
    }
    __syncthreads();

    // ---------------- epilogue: straight from fragments ----------------
    float p0 = 0.f;                     // tr2 (!IS2) or tr3 (IS2)
    float p2 = 0.f, p3 = 0.f;           // tr4, tr5 (IS2 only)
    const int fr = lane >> 2;           // fragment row within 8
    const int fc = (lane & 3) * 2;      // fragment col pair

    if (!IS2) {
#pragma unroll
        for (int mi = 0; mi < 4; mi++)
#pragma unroll
            for (int ni = 0; ni < 4; ni++) {
                int r = wm * 64 + mi * 16 + fr;
                int c = wn * 32 + ni * 8 + fc;
                float a0 = acc[mi][ni][0], a1 = acc[mi][ni][1];
                float a2 = acc[mi][ni][2], a3 = acc[mi][ni][3];
                size_t o = mbase + (size_t)(row0 + r) * MM + col0 + c;
                *(__half2*)&g_B2h[o] = __halves2half2(__float2half_rn(a0), __float2half_rn(a1));
                *(__half2*)&g_B2h[o + 8 * MM] = __halves2half2(__float2half_rn(a2), __float2half_rn(a3));
                if (diag) {
                    if (r == c)         p0 += a0;
                    if (r == c + 1)     p0 += a1;
                    if (r + 8 == c)     p0 += a2;
                    if (r + 8 == c + 1) p0 += a3;
                }
            }
    } else {
#pragma unroll
        for (int mi = 0; mi < 4; mi++)
#pragma unroll
            for (int ni = 0; ni < 4; ni++) {
                int j = wm * 64 + mi * 16 + fr;     // global col0 + j
                int i = wn * 32 + ni * 8 + fc;      // global row0 + i
                float a0 = acc[mi][ni][0], a1 = acc[mi][ni][1];
                float a2 = acc[mi][ni][2], a3 = acc[mi][ni][3];
                size_t o = mbase + (size_t)(col0 + j) * MM + row0 + i;
                float2 av1 = __half22float2(*(const __half2*)&g_Ah[o]);
                float2 bv1 = __half22float2(*(const __half2*)&g_B2h[o]);
                float2 av2 = __half22float2(*(const __half2*)&g_Ah[o + 8 * MM]);
                float2 bv2 = __half22float2(*(const __half2*)&g_B2h[o + 8 * MM]);
                p2 += a0 * av1.x + a1 * av1.y + a2 * av2.x + a3 * av2.y;  // tr(A^4)
                p3 += a0 * bv1.x + a1 * bv1.y + a2 * bv2.x + a3 * bv2.y;  // tr(A^5)
                if (diag) {
                    if (j == i)         p0 += a0;   // tr(A^3)
                    if (j == i + 1)     p0 += a1;
                    if (j + 8 == i)     p0 += a2;
                    if (j + 8 == i + 1) p0 += a3;
                }
            }
    }

    // deterministic block reduce (red reuses ring smem after the sync above)
#pragma unroll
    for (int off = 16; off; off >>= 1) {
        p0 += __shfl_down_sync(0xFFFFFFFFu, p0, off);
        p2 += __shfl_down_sync(0xFFFFFFFFu, p2, off);
        p3 += __shfl_down_sync(0xFFFFFFFFu, p3, off);
    }
    float* red = (float*)sm;
    __syncthreads();
    if (lane == 0) {
        red[w * 3 + 0] = p0; red[w * 3 + 1] = p2; red[w * 3 + 2] = p3;
    }
    __syncthreads();
    if (tid == 0) {
        float s0 = 0.f, s2 = 0.f, s3 = 0.f;
        for (int q = 0; q < 8; q++) {
            s0 += red[q * 3]; s2 += red[q * 3 + 1]; s3 += red[q * 3 + 2];
        }
        int slot = (bc * 4 + (int)(blockIdx.y * 2 + blockIdx.x)) * 4;
        if (!IS2) g_part[slot + 0] = s0;
        else { g_part[slot + 1] = s0; g_part[slot + 2] = s2; g_part[slot + 3] = s3; }
    }
}

// ---------------------------------------------------------------------------
// Combine: out[b] = sum coef[c,i,j] * tr_{i+2}^(j+1) / 65536^(i+j+1)
// ---------------------------------------------------------------------------
__global__ void __launch_bounds__(512) final_kernel(const float* __restrict__ coef,
                                                    float* __restrict__ out) {
    int t = threadIdx.x;
    int b = t >> 4, c = t & 15;
    int bc = b * CHN + c;
    double tr[4];
#pragma unroll
    for (int k = 0; k < 4; k++) {
        float s = 0.f;
#pragma unroll
        for (int tile = 0; tile < 4; tile++) s += g_part[(bc * 4 + tile) * 4 + k];
        tr[k] = (double)s;
    }
    double sum = 0.0;
#pragma unroll
    for (int i = 0; i < 4; i++) {
        double p = tr[i];
        double tp = p;
#pragma unroll
        for (int j = 0; j < 4; j++) {
            double v = ldexp(tp, -16 * (i + j + 1));
            sum += (double)coef[c * 16 + i * 4 + j] * v;
            tp *= p;
        }
    }
#pragma unroll
    for (int off = 8; off; off >>= 1)
        sum += __shfl_down_sync(0xFFFFFFFFu, sum, off, 16);
    if (c == 0) out[b] = (float)sum;
}

extern "C" void kernel_launch(void* const* d_in, const int* in_sizes, int n_in,
                              void* d_out, int out_size) {
    const float* x    = (const float*)d_in[0];
    const float* w    = (const float*)d_in[1];
    const float* bias = (const float*)d_in[2];
    const float* coef = (const float*)d_in[3];
    float* out = (float*)d_out;

    cudaFuncSetAttribute(gemm_kernel<false>, cudaFuncAttributeMaxDynamicSharedMemorySize, GEMM_SMEM);
    cudaFuncSetAttribute(gemm_kernel<true>,  cudaFuncAttributeMaxDynamicSharedMemorySize, GEMM_SMEM);

    conv_kernel<<<dim3(8, 8, BB * 2), dim3(32, 8)>>>(x, w, bias);
    gemm_kernel<false><<<dim3(2, 2, NMAT), 256, GEMM_SMEM>>>();
    gemm_kernel<true> <<<dim3(2, 2, NMAT), 256, GEMM_SMEM>>>();
    final_kernel<<<1, 512>>>(coef, out);
}

// round 14
// speedup vs baseline: 1.4284x; 1.1749x over previous
#include <cuda_runtime.h>
#include <cuda_fp16.h>
#include <cstdint>

#define BB   32
#define CHN  16
#define NN   261
#define MM   256
#define MAT  (MM*MM)
#define NMAT (BB*CHN)

// ---------------- scratch (device globals; no allocs allowed) ----------------
__device__ __align__(256) __half g_Ah  [NMAT * MAT];   // feat fp16 (row-major)
__device__ __align__(256) __half g_B2h [NMAT * MAT];   // B2 row-major fp16
__device__ float g_part[NMAT * 4 * 4];   // [bc][tile 2x2][k: tr2,tr3,tr4,tr5]

// ---------------------------- helpers ---------------------------------------
__device__ __forceinline__ uint32_t smem_u32(const void* p) {
    uint32_t a;
    asm("{ .reg .u64 t; cvta.to.shared.u64 t, %1; cvt.u32.u64 %0, t; }" : "=r"(a) : "l"(p));
    return a;
}
#define CP16(dst, src) asm volatile("cp.async.cg.shared.global [%0], [%1], 16;" :: "r"((uint32_t)(dst)), "l"(src))
#define CP_COMMIT()    asm volatile("cp.async.commit_group;" ::: "memory")
#define CP_WAIT(n)     asm volatile("cp.async.wait_group %0;" :: "n"(n) : "memory")

#define MMA_F16(d, a, b) \
    asm volatile("mma.sync.aligned.m16n8k16.row.col.f32.f16.f16.f32 " \
        "{%0,%1,%2,%3},{%4,%5,%6,%7},{%8,%9},{%0,%1,%2,%3};" \
        : "+f"((d)[0]), "+f"((d)[1]), "+f"((d)[2]), "+f"((d)[3]) \
        : "r"((a)[0]), "r"((a)[1]), "r"((a)[2]), "r"((a)[3]), "r"((b)[0]), "r"((b)[1]))

#define LDSM4(r, addr) \
    asm volatile("ldmatrix.sync.aligned.m8n8.x4.shared.b16 {%0,%1,%2,%3}, [%4];" \
        : "=r"((r)[0]), "=r"((r)[1]), "=r"((r)[2]), "=r"((r)[3]) : "r"(addr))

#define LDSM4T(r, addr) \
    asm volatile("ldmatrix.sync.aligned.m8n8.x4.trans.shared.b16 {%0,%1,%2,%3}, [%4];" \
        : "=r"((r)[0]), "=r"((r)[1]), "=r"((r)[2]), "=r"((r)[3]) : "r"(addr))

// ---------------------------------------------------------------------------
// Conv via implicit GEMM on tensor cores.
// Tile: 16 rows x 32 cols of outputs (512) per block, all 16 channels.
// P[512][56] fp16 patches (k = p*6+q, 36 real + zero pad to 48), W[16][56].
// out[512x16] = P @ W^T, m16n8k16 MMAs, +bias, staged to smem, coalesced out.
// ---------------------------------------------------------------------------
#define CV_PADK 56
#define CV_P    0              // 512*56*2 = 57344 (aliased by out_s after MMA)
#define CV_XS   57344          // [21][40] half = 1680 -> 59024
#define CV_WS   59040          // [16][56] half = 1792 -> 60832
#define CV_BS   60832          // 16 floats -> 60896
#define CV_SMEM 60896
#define CV_OS   18             // out_s stride in halves per output

__global__ void __launch_bounds__(256, 2) conv_kernel(const float* __restrict__ x,
                                                      const float* __restrict__ w,
                                                      const float* __restrict__ bias) {
    extern __shared__ char sm[];
    __half* P   = (__half*)(sm + CV_P);
    __half* xs  = (__half*)(sm + CV_XS);    // [21][40]
    __half* ws  = (__half*)(sm + CV_WS);    // [16][56]
    float*  bs  = (float*)(sm + CV_BS);
    const uint32_t sbase = smem_u32(sm);
    const int b  = blockIdx.z;
    const int by = blockIdx.y;              // output rows by*16..+15
    const int bx = blockIdx.x;              // output cols bx*32..+31
    const int tid = threadIdx.x;
    const int lane = tid & 31, wp = tid >> 5;

    for (int i = tid; i < 21 * 37; i += 256) {
        int r = i / 37, c = i % 37;
        xs[r * 40 + c] = __float2half_rn(x[b * NN * NN + (by * 16 + r) * NN + bx * 32 + c]);
    }
    for (int i = tid; i < 16 * CV_PADK; i += 256) {
        int k = i % CV_PADK;
        ws[i] = (k < 36) ? __float2half_rn(w[(i / CV_PADK) * 36 + k]) : __float2half_rn(0.f);
    }
    if (tid < 16) bs[tid] = bias[tid];
    __syncthreads();

    // build patches: 2 outputs per thread
#pragma unroll
    for (int it = 0; it < 2; it++) {
        int o = it * 256 + tid;
        int r = o >> 5, c = o & 31;
        __half* Po = P + o * CV_PADK;
#pragma unroll
        for (int p = 0; p < 6; p++) {
            const __half* xr = xs + (r + p) * 40 + c;
#pragma unroll
            for (int j = 0; j < 3; j++)
                *(__half2*)&Po[p * 6 + 2 * j] = __halves2half2(xr[2 * j], xr[2 * j + 1]);
        }
#pragma unroll
        for (int j = 0; j < 6; j++)
            *(__half2*)&Po[36 + 2 * j] = __halves2half2(__float2half_rn(0.f), __float2half_rn(0.f));
    }
    __syncthreads();

    // weights fragments (fixed per warp): B-op = rows [n=ch][k], non-trans ldmatrix
    uint32_t bq[3][4];
    {
        uint32_t wOff = sbase + CV_WS
                      + (uint32_t)(((lane & 7) + ((lane >> 4) << 3)) * (CV_PADK * 2)
                      + ((lane >> 3) & 1) * 16);
#pragma unroll
        for (int k = 0; k < 3; k++) LDSM4(bq[k], wOff + (uint32_t)(k * 32));
    }

    const uint32_t aOff = sbase + CV_P
                        + (uint32_t)(((lane & 15) * CV_PADK + ((lane >> 4) << 3)) * 2)
                        + (uint32_t)(wp * 64 * CV_PADK * 2);
    float acc[4][2][4];
#pragma unroll
    for (int mi = 0; mi < 4; mi++)
#pragma unroll
        for (int ni = 0; ni < 2; ni++)
#pragma unroll
            for (int e = 0; e < 4; e++) acc[mi][ni][e] = 0.f;

#pragma unroll
    for (int mi = 0; mi < 4; mi++) {
#pragma unroll
        for (int k = 0; k < 3; k++) {
            uint32_t af[4];
            LDSM4(af, aOff + (uint32_t)(mi * 16 * CV_PADK * 2 + k * 32));
            MMA_F16(acc[mi][0], af, &bq[k][0]);
            MMA_F16(acc[mi][1], af, &bq[k][2]);
        }
    }
    __syncthreads();      // P dead; alias out_s over it

    __half* outs = (__half*)(sm + CV_P);    // [512][CV_OS]
    const int fr = lane >> 2, fc = (lane & 3) * 2;
#pragma unroll
    for (int mi = 0; mi < 4; mi++) {
        int o = wp * 64 + mi * 16 + fr;
#pragma unroll
        for (int ni = 0; ni < 2; ni++) {
            int ch = ni * 8 + fc;
            float b0 = bs[ch], b1 = bs[ch + 1];
            *(__half2*)&outs[o * CV_OS + ch] =
                __halves2half2(__float2half_rn(acc[mi][ni][0] + b0),
                               __float2half_rn(acc[mi][ni][1] + b1));
            *(__half2*)&outs[(o + 8) * CV_OS + ch] =
                __halves2half2(__float2half_rn(acc[mi][ni][2] + b0),
                               __float2half_rn(acc[mi][ni][3] + b1));
        }
    }
    __syncthreads();

    // coalesced copy-out: u -> (ch, chunk of 8 consecutive outputs)
#pragma unroll
    for (int it = 0; it < 4; it++) {
        int u = it * 256 + tid;
        int ch = (u >> 2) & 15;
        int chunk = (u & 3) + ((u >> 6) << 2);
        int o0 = chunk * 8;
        int r = o0 >> 5, c0 = o0 & 31;
        __half tmp[8];
#pragma unroll
        for (int i = 0; i < 8; i++) tmp[i] = outs[(o0 + i) * CV_OS + ch];
        size_t dst = (size_t)(b * CHN + ch) * MAT + (size_t)(by * 16 + r) * MM + bx * 32 + c0;
        *(uint4*)&g_Ah[dst] = *(uint4*)tmp;
    }
}

// ---------------------------------------------------------------------------
// fp16 mma.sync GEMM, 128x128 tile, BK=32, 4-stage cp.async ring, no epilogue
// staging. (unchanged from R12)
// ---------------------------------------------------------------------------
#define PADK    40
#define PADN    136
#define OFFB    10240u
#define SB      18944u
#define GEMM_SMEM 75776

__device__ __forceinline__ void load_stage(uint32_t st,
        const __half* __restrict__ Ah, const __half* __restrict__ Bsrc,
        int col0, int kb, int tid) {
#pragma unroll
    for (int it = 0; it < 2; ++it) {
        int u = it * 256 + tid;
        int rowA = u >> 2, segA = u & 3;
        uint32_t da = (uint32_t)(rowA * (PADK * 2) + segA * 16);
        CP16(st + da, Ah + rowA * MM + kb * 32 + segA * 8);
        int rowB = u >> 4, segB = u & 15;
        uint32_t db = (uint32_t)(rowB * (PADN * 2) + segB * 16);
        CP16(st + OFFB + db, Bsrc + (size_t)(kb * 32 + rowB) * MM + col0 + segB * 8);
    }
}

template <bool IS2>
__global__ void __launch_bounds__(256, 2) gemm_kernel() {
    extern __shared__ char sm[];
    const uint32_t sbase = smem_u32(sm);
    const int tid  = threadIdx.x;
    const int lane = tid & 31;
    const int w    = tid >> 5;
    const int wm   = w >> 2;
    const int wn   = w & 3;
    const int bc   = blockIdx.z;
    const int row0 = blockIdx.y * 128;
    const int col0 = blockIdx.x * 128;
    const bool diag = (blockIdx.x == blockIdx.y);
    const size_t mbase = (size_t)bc * MAT;

    const __half* Ah = g_Ah + mbase + (size_t)row0 * MM;
    const __half* Bsrc = (IS2 ? g_B2h : g_Ah) + mbase;

    uint32_t aOff, bOff;
    if (!IS2) {
        aOff = (uint32_t)(((lane & 15) * PADK + ((lane >> 4) << 3)) * 2)
             + (uint32_t)(wm * 64 * PADK * 2);
        bOff = OFFB
             + (uint32_t)(((lane & 7) + ((lane >> 3) & 1) * 8) * (PADN * 2)
             + (wn * 32 + (lane >> 4) * 8) * 2);
    } else {
        aOff = OFFB
             + (uint32_t)(((lane & 7) + ((lane >> 4) << 3)) * (PADN * 2)
             + (wm * 64 + ((lane >> 3) & 1) * 8) * 2);
        bOff = (uint32_t)((wn * 32 + (lane & 7) + ((lane >> 4) << 3)) * (PADK * 2)
             + ((lane >> 3) & 1) * 16);
    }

    float acc[4][4][4];
#pragma unroll
    for (int mi = 0; mi < 4; mi++)
#pragma unroll
        for (int ni = 0; ni < 4; ni++)
#pragma unroll
            for (int e = 0; e < 4; e++) acc[mi][ni][e] = 0.f;

    load_stage(sbase + 0 * SB, Ah, Bsrc, col0, 0, tid); CP_COMMIT();
    load_stage(sbase + 1 * SB, Ah, Bsrc, col0, 1, tid); CP_COMMIT();
    load_stage(sbase + 2 * SB, Ah, Bsrc, col0, 2, tid); CP_COMMIT();

    for (int kb = 0; kb < 8; ++kb) {
        if (kb < 6) { CP_WAIT(2); }
        else if (kb == 6) { CP_WAIT(1); }
        else { CP_WAIT(0); }
        __syncthreads();
        if (kb + 3 < 8) {
            load_stage(sbase + (uint32_t)((kb + 3) & 3) * SB, Ah, Bsrc, col0, kb + 3, tid);
            CP_COMMIT();
        }

        const uint32_t st = sbase + (uint32_t)(kb & 3) * SB;

#pragma unroll
        for (int ks = 0; ks < 2; ++ks) {
            uint32_t af[4][4], bq[2][4];
            if (!IS2) {
#pragma unroll
                for (int mi = 0; mi < 4; mi++)
                    LDSM4(af[mi], st + aOff + (uint32_t)(mi * 16 * PADK * 2 + ks * 32));
#pragma unroll
                for (int q = 0; q < 2; q++)
                    LDSM4T(bq[q], st + bOff + (uint32_t)(ks * 16 * PADN * 2 + q * 16 * 2));
            } else {
#pragma unroll
                for (int mi = 0; mi < 4; mi++)
                    LDSM4T(af[mi], st + aOff + (uint32_t)(ks * 16 * PADN * 2 + mi * 16 * 2));
#pragma unroll
                for (int q = 0; q < 2; q++)
                    LDSM4(bq[q], st + bOff + (uint32_t)(q * 16 * PADK * 2 + ks * 32));
            }
#pragma unroll
            for (int mi = 0; mi < 4; mi++)
#pragma unroll
                for (int ni = 0; ni < 4; ni++)
                    MMA_F16(acc[mi][ni], af[mi], &bq[ni >> 1][(ni & 1) * 2]);
        }
    }
    __syncthreads();

    float p0 = 0.f, p2 = 0.f, p3 = 0.f;
    const int fr = lane >> 2;
    const int fc = (lane & 3) * 2;

    if (!IS2) {
#pragma unroll
        for (int mi = 0; mi < 4; mi++)
#pragma unroll
            for (int ni = 0; ni < 4; ni++) {
                int r = wm * 64 + mi * 16 + fr;
                int c = wn * 32 + ni * 8 + fc;
                float a0 = acc[mi][ni][0], a1 = acc[mi][ni][1];
                float a2 = acc[mi][ni][2], a3 = acc[mi][ni][3];
                size_t o = mbase + (size_t)(row0 + r) * MM + col0 + c;
                *(__half2*)&g_B2h[o] = __halves2half2(__float2half_rn(a0), __float2half_rn(a1));
                *(__half2*)&g_B2h[o + 8 * MM] = __halves2half2(__float2half_rn(a2), __float2half_rn(a3));
                if (diag) {
                    if (r == c)         p0 += a0;
                    if (r == c + 1)     p0 += a1;
                    if (r + 8 == c)     p0 += a2;
                    if (r + 8 == c + 1) p0 += a3;
                }
            }
    } else {
#pragma unroll
        for (int mi = 0; mi < 4; mi++)
#pragma unroll
            for (int ni = 0; ni < 4; ni++) {
                int j = wm * 64 + mi * 16 + fr;
                int i = wn * 32 + ni * 8 + fc;
                float a0 = acc[mi][ni][0], a1 = acc[mi][ni][1];
                float a2 = acc[mi][ni][2], a3 = acc[mi][ni][3];
                size_t o = mbase + (size_t)(col0 + j) * MM + row0 + i;
                float2 av1 = __half22float2(*(const __half2*)&g_Ah[o]);
                float2 bv1 = __half22float2(*(const __half2*)&g_B2h[o]);
                float2 av2 = __half22float2(*(const __half2*)&g_Ah[o + 8 * MM]);
                float2 bv2 = __half22float2(*(const __half2*)&g_B2h[o + 8 * MM]);
                p2 += a0 * av1.x + a1 * av1.y + a2 * av2.x + a3 * av2.y;
                p3 += a0 * bv1.x + a1 * bv1.y + a2 * bv2.x + a3 * bv2.y;
                if (diag) {
                    if (j == i)         p0 += a0;
                    if (j == i + 1)     p0 += a1;
                    if (j + 8 == i)     p0 += a2;
                    if (j + 8 == i + 1) p0 += a3;
                }
            }
    }

#pragma unroll
    for (int off = 16; off; off >>= 1) {
        p0 += __shfl_down_sync(0xFFFFFFFFu, p0, off);
        p2 += __shfl_down_sync(0xFFFFFFFFu, p2, off);
        p3 += __shfl_down_sync(0xFFFFFFFFu, p3, off);
    }
    float* red = (float*)sm;
    __syncthreads();
    if (lane == 0) {
        red[w * 3 + 0] = p0; red[w * 3 + 1] = p2; red[w * 3 + 2] = p3;
    }
    __syncthreads();
    if (tid == 0) {
        float s0 = 0.f, s2 = 0.f, s3 = 0.f;
        for (int q = 0; q < 8; q++) {
            s0 += red[q * 3]; s2 += red[q * 3 + 1]; s3 += red[q * 3 + 2];
        }
        int slot = (bc * 4 + (int)(blockIdx.y * 2 + blockIdx.x)) * 4;
        if (!IS2) g_part[slot + 0] = s0;
        else { g_part[slot + 1] = s0; g_part[slot + 2] = s2; g_part[slot + 3] = s3; }
    }
}

// ---------------------------------------------------------------------------
// Combine: out[b] = sum coef[c,i,j] * tr_{i+2}^(j+1) / 65536^(i+j+1)
// ---------------------------------------------------------------------------
__global__ void __launch_bounds__(512) final_kernel(const float* __restrict__ coef,
                                                    float* __restrict__ out) {
    int t = threadIdx.x;
    int b = t >> 4, c = t & 15;
    int bc = b * CHN + c;
    double tr[4];
#pragma unroll
    for (int k = 0; k < 4; k++) {
        float s = 0.f;
#pragma unroll
        for (int tile = 0; tile < 4; tile++) s += g_part[(bc * 4 + tile) * 4 + k];
        tr[k] = (double)s;
    }
    double sum = 0.0;
#pragma unroll
    for (int i = 0; i < 4; i++) {
        double p = tr[i];
        double tp = p;
#pragma unroll
        for (int j = 0; j < 4; j++) {
            double v = ldexp(tp, -16 * (i + j + 1));
            sum += (double)coef[c * 16 + i * 4 + j] * v;
            tp *= p;
        }
    }
#pragma unroll
    for (int off = 8; off; off >>= 1)
        sum += __shfl_down_sync(0xFFFFFFFFu, sum, off, 16);
    if (c == 0) out[b] = (float)sum;
}

extern "C" void kernel_launch(void* const* d_in, const int* in_sizes, int n_in,
                              void* d_out, int out_size) {
    const float* x    = (const float*)d_in[0];
    const float* w    = (const float*)d_in[1];
    const float* bias = (const float*)d_in[2];
    const float* coef = (const float*)d_in[3];
    float* out = (float*)d_out;

    cudaFuncSetAttribute(conv_kernel, cudaFuncAttributeMaxDynamicSharedMemorySize, CV_SMEM);
    cudaFuncSetAttribute(gemm_kernel<false>, cudaFuncAttributeMaxDynamicSharedMemorySize, GEMM_SMEM);
    cudaFuncSetAttribute(gemm_kernel<true>,  cudaFuncAttributeMaxDynamicSharedMemorySize, GEMM_SMEM);

    conv_kernel<<<dim3(8, 16, BB), 256, CV_SMEM>>>(x, w, bias);
    gemm_kernel<false><<<dim3(2, 2, NMAT), 256, GEMM_SMEM>>>();
    gemm_kernel<true> <<<dim3(2, 2, NMAT), 256, GEMM_SMEM>>>();
    final_kernel<<<1, 512>>>(coef, out);
}